// round 5
// baseline (speedup 1.0000x reference)
#include <cuda_runtime.h>
#include <math_constants.h>

#define Bn 16
#define Nn 256
#define Rr 24
#define Ll 32
#define CLU 8            // CTAs per cluster (one cluster per batch)
#define THR 1024

// Scratch (device globals; no allocation allowed)
__device__ float  g_dist[Bn * Nn * Nn];            // edge/dist matrix
__device__ float  g_hops[Bn * Nn * Nn];
__device__ float  g_stageD[2][Bn][Nn];             // column-k broadcast, ping-pong
__device__ float  g_stageH[2][Bn][Nn];
__device__ double g_acc[160];                      // double accumulators

// Output layout (flattened tuple, float32):
#define OFF_TDT  0
#define OFF_TRT  16
#define OFF_TAT  32
#define OFF_TD   96
#define OFF_UNS  112
#define OFF_TTR  128
#define OFF_TT   144
#define OFF_NDIS (144 + Bn * Nn * Nn)
// g_acc layout: [0..143] same as out scalars, [144..159] n_disconnected

// ---------------------------------------------------------------------------
// Init: edge matrix = +INF, zero double accumulators
// ---------------------------------------------------------------------------
__global__ void k_init() {
    int idx = blockIdx.x * blockDim.x + threadIdx.x;   // exactly B*N*N threads
    g_dist[idx] = CUDART_INF_F;
    if (idx < 160) g_acc[idx] = 0.0;
}

// ---------------------------------------------------------------------------
// Edge build: one warp per (batch, route).
// Cumsum: XLA ReduceWindowRewriter blocked association, base_length = 16:
//   scan[m] = seq(a[0..m])                    for m < 16
//   scan[m] = fadd( seq(a[0..15]), seq(a[16..m]) )   for m >= 16
// ---------------------------------------------------------------------------
__global__ void k_edges(const float* __restrict__ dtm,
                        const int*   __restrict__ routes) {
    int br = blockIdx.x;
    int b = br / Rr;
    int lane = threadIdx.x;

    __shared__ int   ss[Ll];
    __shared__ float lf[Ll], lr[Ll];
    __shared__ float cf[Ll], cr[Ll];

    const int* rt = routes + br * Ll;
    int s = rt[lane];
    ss[lane] = s;
    __syncwarp();

    int snext = ss[(lane + 1 < Ll) ? lane + 1 : Ll - 1];
    float vf = 0.0f, vr = 0.0f;
    if (lane < Ll - 1) {
        vf = __fadd_rn(dtm[(b * Nn + s) * Nn + snext], 60.0f);
        vr = __fadd_rn(dtm[(b * Nn + snext) * Nn + s], 60.0f);
    }
    lf[lane] = vf;
    lr[lane] = vr;
    __syncwarp();

    if (lane == 0) {
        cf[0] = 0.0f; cr[0] = 0.0f;
        float a0f = 0.0f, a1f = 0.0f, Tf = 0.0f;
        float a0r = 0.0f, a1r = 0.0f, Tr = 0.0f;
        double srt = 0.0;
        #pragma unroll
        for (int m = 0; m < Ll - 1; m++) {
            if (m < 16) {
                a0f = __fadd_rn(a0f, lf[m]);
                a0r = __fadd_rn(a0r, lr[m]);
                cf[m + 1] = a0f;
                cr[m + 1] = a0r;
                if (m == 15) { Tf = a0f; Tr = a0r; }
            } else {
                a1f = __fadd_rn(a1f, lf[m]);
                a1r = __fadd_rn(a1r, lr[m]);
                cf[m + 1] = __fadd_rn(Tf, a1f);
                cr[m + 1] = __fadd_rn(Tr, a1r);
            }
            srt += (double)lf[m] + (double)lr[m];
        }
        atomicAdd(&g_acc[OFF_TRT + b], srt);       // total route time (double)
    }
    __syncwarp();

    unsigned int* eU = reinterpret_cast<unsigned int*>(g_dist);
    for (int p = lane; p < Ll * Ll; p += 32) {
        int i = p >> 5, j = p & 31;
        if (i < j) {
            int si = ss[i], sj = ss[j];
            float tf = __fsub_rn(cf[j], cf[i]);
            atomicMin(&eU[(b * Nn + si) * Nn + sj], __float_as_uint(tf));
            float tr = __fsub_rn(cr[j], cr[i]);
            atomicMin(&eU[(b * Nn + sj) * Nn + si], __float_as_uint(tr));
        }
    }
}

// ---------------------------------------------------------------------------
// Diagonal -> 0, hops init
// ---------------------------------------------------------------------------
__global__ void k_diag_hops() {
    int idx = blockIdx.x * blockDim.x + threadIdx.x;   // B*N*N threads
    int j = idx & (Nn - 1);
    int i = (idx >> 8) & (Nn - 1);
    float d = g_dist[idx];
    if (i == j) { d = 0.0f; g_dist[idx] = 0.0f; }
    g_hops[idx] = (i != j && d != CUDART_INF_F) ? 1.0f : 0.0f;
}

// ---------------------------------------------------------------------------
// Exact-schedule Floyd-Warshall: k sequential, cluster of 8 CTAs per batch.
// CTA c owns columns [32c, 32c+32) x all 256 rows; 8 cells/thread in regs.
// Fused epilogue computes trip_times and all demand reductions (double acc).
// ---------------------------------------------------------------------------
__device__ __forceinline__ void relax(float& dm, float& hm,
                                      float cdv, float chv,
                                      float rd, float rh) {
    float alt = __fadd_rn(cdv, rd);
    float nh  = chv + rh;
    if (alt < dm) { dm = alt; hm = nh; }
}

__device__ __forceinline__ double warp_sum_d(double v) {
    #pragma unroll
    for (int o = 16; o; o >>= 1) v += __shfl_down_sync(0xffffffffu, v, o);
    return v;
}

#define CLUSTER_SYNC_() do { \
    asm volatile("barrier.cluster.arrive.aligned;" ::: "memory"); \
    asm volatile("barrier.cluster.wait.aligned;" ::: "memory"); \
} while (0)

__global__ void __cluster_dims__(CLU, 1, 1) __launch_bounds__(THR, 1)
fw_exact(const float* __restrict__ demand, float* __restrict__ out) {
    int b = blockIdx.x / CLU;
    int c = blockIdx.x % CLU;
    int t = threadIdx.x;
    int j = t & 31;            // local column 0..31
    int rb = t >> 5;           // row block 0..31
    int r0 = rb << 3;          // first of 8 owned rows
    int jg = c * 32 + j;       // global column

    __shared__ float rowD[2][32], rowH[2][32];

    // Load 8 owned cells into registers
    float d[8], h[8];
    int base = b * Nn * Nn + r0 * Nn + jg;
    #pragma unroll
    for (int m = 0; m < 8; m++) {
        d[m] = g_dist[base + m * Nn];
        h[m] = g_hops[base + m * Nn];
    }

    // Pre-post row 0 (intra-CTA) and column 0 (cluster-wide via L2 staging)
    if (rb == 0) { rowD[0][j] = d[0]; rowH[0][j] = h[0]; }
    if (c == 0 && j == 0) {
        float4 v0 = make_float4(d[0], d[1], d[2], d[3]);
        float4 v1 = make_float4(d[4], d[5], d[6], d[7]);
        __stcg(reinterpret_cast<float4*>(&g_stageD[0][b][r0]),     v0);
        __stcg(reinterpret_cast<float4*>(&g_stageD[0][b][r0 + 4]), v1);
        float4 w0 = make_float4(h[0], h[1], h[2], h[3]);
        float4 w1 = make_float4(h[4], h[5], h[6], h[7]);
        __stcg(reinterpret_cast<float4*>(&g_stageH[0][b][r0]),     w0);
        __stcg(reinterpret_cast<float4*>(&g_stageH[0][b][r0 + 4]), w1);
    }
    CLUSTER_SYNC_();

    for (int k = 0; k < Nn; k++) {
        int p = k & 1;
        // column k for my 8 rows (L2, bypass L1)
        float4 cd0 = __ldcg(reinterpret_cast<const float4*>(&g_stageD[p][b][r0]));
        float4 cd1 = __ldcg(reinterpret_cast<const float4*>(&g_stageD[p][b][r0 + 4]));
        float4 ch0 = __ldcg(reinterpret_cast<const float4*>(&g_stageH[p][b][r0]));
        float4 ch1 = __ldcg(reinterpret_cast<const float4*>(&g_stageH[p][b][r0 + 4]));
        // row k at my column (intra-CTA smem)
        float rd = rowD[p][j];
        float rh = rowH[p][j];

        relax(d[0], h[0], cd0.x, ch0.x, rd, rh);
        relax(d[1], h[1], cd0.y, ch0.y, rd, rh);
        relax(d[2], h[2], cd0.z, ch0.z, rd, rh);
        relax(d[3], h[3], cd0.w, ch0.w, rd, rh);
        relax(d[4], h[4], cd1.x, ch1.x, rd, rh);
        relax(d[5], h[5], cd1.y, ch1.y, rd, rh);
        relax(d[6], h[6], cd1.z, ch1.z, rd, rh);
        relax(d[7], h[7], cd1.w, ch1.w, rd, rh);

        // post row k+1 (self-guarding: rb==32 never true at k=255)
        int kn = k + 1;
        if (rb == (kn >> 3)) {
            rowD[p ^ 1][j] = d[kn & 7];
            rowH[p ^ 1][j] = h[kn & 7];
        }
        // post column k+1 (owner CTA only; c==8 never true at k=255)
        if (c == (kn >> 5) && j == (kn & 31)) {
            float4 v0 = make_float4(d[0], d[1], d[2], d[3]);
            float4 v1 = make_float4(d[4], d[5], d[6], d[7]);
            __stcg(reinterpret_cast<float4*>(&g_stageD[p ^ 1][b][r0]),     v0);
            __stcg(reinterpret_cast<float4*>(&g_stageD[p ^ 1][b][r0 + 4]), v1);
            float4 w0 = make_float4(h[0], h[1], h[2], h[3]);
            float4 w1 = make_float4(h[4], h[5], h[6], h[7]);
            __stcg(reinterpret_cast<float4*>(&g_stageH[p ^ 1][b][r0]),     w0);
            __stcg(reinterpret_cast<float4*>(&g_stageH[p ^ 1][b][r0 + 4]), w1);
        }
        CLUSTER_SYNC_();
    }

    // ---- fused epilogue: trip_times + reductions (double accumulation) ----
    double a_dt = 0, a_tr = 0, a_un = 0, a_td = 0, a_nd = 0;
    double a_b0 = 0, a_b1 = 0, a_b2 = 0, a_du = 0;

    #pragma unroll
    for (int m = 0; m < 8; m++) {
        int gi = base + m * Nn;
        float dd = d[m];
        float hh = h[m];
        float dem = demand[gi];
        bool np = (dd == CUDART_INF_F);
        float pl = np ? 0.0f : __fadd_rn(hh, 1.0f);
        float tr = (pl == 0.0f) ? 0.0f : __fsub_rn(pl, 2.0f);
        float tt = np ? 0.0f : __fadd_rn(dd, __fmul_rn(tr, 300.0f));
        out[OFF_TT + gi] = tt;
        double ddem = (double)dem;
        a_dt += ddem * (double)tt;
        a_tr += ddem * (double)tr;
        a_td += ddem;
        if (np) { a_un += ddem; if (dem > 0.0f) a_nd += 1.0; }
        if (tr == 0.0f)      a_b0 += ddem;
        else if (tr == 1.0f) a_b1 += ddem;
        else if (tr == 2.0f) a_b2 += ddem;
        else if (tr > 2.0f)  a_du += ddem;
    }

    a_dt = warp_sum_d(a_dt); a_tr = warp_sum_d(a_tr); a_un = warp_sum_d(a_un);
    a_td = warp_sum_d(a_td); a_nd = warp_sum_d(a_nd); a_b0 = warp_sum_d(a_b0);
    a_b1 = warp_sum_d(a_b1); a_b2 = warp_sum_d(a_b2); a_du = warp_sum_d(a_du);

    if (j == 0) {   // lane 0 of each warp
        atomicAdd(&g_acc[OFF_TDT + b], a_dt);
        atomicAdd(&g_acc[OFF_TTR + b], a_tr);
        atomicAdd(&g_acc[OFF_UNS + b], a_un);
        atomicAdd(&g_acc[OFF_TD  + b], a_td);
        atomicAdd(&g_acc[144 + b],     a_nd);
        atomicAdd(&g_acc[OFF_TAT + b * 4 + 0], a_b0);
        atomicAdd(&g_acc[OFF_TAT + b * 4 + 1], a_b1);
        atomicAdd(&g_acc[OFF_TAT + b * 4 + 2], a_b2);
        atomicAdd(&g_acc[OFF_TAT + b * 4 + 3], a_du + a_un);
    }
}

// ---------------------------------------------------------------------------
// Convert double accumulators to float outputs
// ---------------------------------------------------------------------------
__global__ void k_final(float* out) {
    int t = threadIdx.x;        // 160 threads
    if (t < 144)      out[t] = (float)g_acc[t];
    else if (t < 160) out[OFF_NDIS + (t - 144)] = (float)g_acc[t];
}

// ---------------------------------------------------------------------------
extern "C" void kernel_launch(void* const* d_in, const int* in_sizes, int n_in,
                              void* d_out, int out_size) {
    const float* dtm    = (const float*)d_in[0];
    const float* demand = (const float*)d_in[1];
    const int*   routes = (const int*)d_in[2];
    float* out = (float*)d_out;

    k_init<<<(Bn * Nn * Nn) / 256, 256>>>();
    k_edges<<<Bn * Rr, 32>>>(dtm, routes);
    k_diag_hops<<<(Bn * Nn * Nn) / 256, 256>>>();
    fw_exact<<<Bn * CLU, THR>>>(demand, out);
    k_final<<<1, 160>>>(out);
}

// round 6
// speedup vs baseline: 1.8493x; 1.8493x over previous
#include <cuda_runtime.h>
#include <math_constants.h>

#define Bn 16
#define Nn 256
#define Rr 24
#define Ll 32
#define CLU 8            // CTAs per cluster (one cluster per batch)
#define THR 1024
#define Gg 8             // k-steps per cluster sync
#define NGRP (Nn / Gg)   // 32 groups

// Scratch (device globals; no allocation allowed)
__device__ float  g_dist[Bn * Nn * Nn];            // edge/dist matrix
__device__ float  g_stageD[2][Bn][Gg][Nn];         // column-strip broadcast, ping-pong
__device__ float  g_stageH[2][Bn][Gg][Nn];
__device__ double g_acc[160];                      // double accumulators

// Output layout (flattened tuple, float32):
#define OFF_TDT  0
#define OFF_TRT  16
#define OFF_TAT  32
#define OFF_TD   96
#define OFF_UNS  112
#define OFF_TTR  128
#define OFF_TT   144
#define OFF_NDIS (144 + Bn * Nn * Nn)
// g_acc layout: [0..143] same as out scalars, [144..159] n_disconnected

// ---------------------------------------------------------------------------
// Init: edge matrix = +INF, zero double accumulators
// ---------------------------------------------------------------------------
__global__ void k_init() {
    int idx = blockIdx.x * blockDim.x + threadIdx.x;   // exactly B*N*N threads
    g_dist[idx] = CUDART_INF_F;
    if (idx < 160) g_acc[idx] = 0.0;
}

// ---------------------------------------------------------------------------
// Edge build: one warp per (batch, route).
// Cumsum: XLA ReduceWindowRewriter blocked association, base_length = 16:
//   scan[m] = seq(a[0..m])                    for m < 16
//   scan[m] = fadd( seq(a[0..15]), seq(a[16..m]) )   for m >= 16
// ---------------------------------------------------------------------------
__global__ void k_edges(const float* __restrict__ dtm,
                        const int*   __restrict__ routes) {
    int br = blockIdx.x;
    int b = br / Rr;
    int lane = threadIdx.x;

    __shared__ int   ss[Ll];
    __shared__ float lf[Ll], lr[Ll];
    __shared__ float cf[Ll], cr[Ll];

    const int* rt = routes + br * Ll;
    int s = rt[lane];
    ss[lane] = s;
    __syncwarp();

    int snext = ss[(lane + 1 < Ll) ? lane + 1 : Ll - 1];
    float vf = 0.0f, vr = 0.0f;
    if (lane < Ll - 1) {
        vf = __fadd_rn(dtm[(b * Nn + s) * Nn + snext], 60.0f);
        vr = __fadd_rn(dtm[(b * Nn + snext) * Nn + s], 60.0f);
    }
    lf[lane] = vf;
    lr[lane] = vr;
    __syncwarp();

    if (lane == 0) {
        cf[0] = 0.0f; cr[0] = 0.0f;
        float a0f = 0.0f, a1f = 0.0f, Tf = 0.0f;
        float a0r = 0.0f, a1r = 0.0f, Tr = 0.0f;
        double srt = 0.0;
        #pragma unroll
        for (int m = 0; m < Ll - 1; m++) {
            if (m < 16) {
                a0f = __fadd_rn(a0f, lf[m]);
                a0r = __fadd_rn(a0r, lr[m]);
                cf[m + 1] = a0f;
                cr[m + 1] = a0r;
                if (m == 15) { Tf = a0f; Tr = a0r; }
            } else {
                a1f = __fadd_rn(a1f, lf[m]);
                a1r = __fadd_rn(a1r, lr[m]);
                cf[m + 1] = __fadd_rn(Tf, a1f);
                cr[m + 1] = __fadd_rn(Tr, a1r);
            }
            srt += (double)lf[m] + (double)lr[m];
        }
        atomicAdd(&g_acc[OFF_TRT + b], srt);       // total route time (double)
    }
    __syncwarp();

    unsigned int* eU = reinterpret_cast<unsigned int*>(g_dist);
    for (int p = lane; p < Ll * Ll; p += 32) {
        int i = p >> 5, j = p & 31;
        if (i < j) {
            int si = ss[i], sj = ss[j];
            float tf = __fsub_rn(cf[j], cf[i]);
            atomicMin(&eU[(b * Nn + si) * Nn + sj], __float_as_uint(tf));
            float tr = __fsub_rn(cr[j], cr[i]);
            atomicMin(&eU[(b * Nn + sj) * Nn + si], __float_as_uint(tr));
        }
    }
}

// ---------------------------------------------------------------------------
// Exact-schedule Floyd-Warshall, G=8 steps per cluster sync.
// Cluster of 8 CTAs per batch; CTA c owns columns [32c, 32c+32); each thread
// holds 8 (dist,hops) cells in registers. Per group: owner publishes its 8
// columns at (k0-1)-completion; every CTA strip-completes them locally
// (bit-exact recurrence). Fused epilogue does all reductions (double acc).
// ---------------------------------------------------------------------------
__device__ __forceinline__ double warp_sum_d(double v) {
    #pragma unroll
    for (int o = 16; o; o >>= 1) v += __shfl_down_sync(0xffffffffu, v, o);
    return v;
}

#define CLUSTER_SYNC_() do { \
    asm volatile("barrier.cluster.arrive.aligned;" ::: "memory"); \
    asm volatile("barrier.cluster.wait.aligned;" ::: "memory"); \
} while (0)

__global__ void __cluster_dims__(CLU, 1, 1) __launch_bounds__(THR, 1)
fw_exact(const float* __restrict__ demand, float* __restrict__ out) {
    int b = blockIdx.x / CLU;
    int c = blockIdx.x % CLU;
    int t = threadIdx.x;
    int j = t & 31;            // local column 0..31
    int rb = t >> 5;           // row block 0..31
    int r0 = rb << 3;          // first of 8 owned rows
    int jg = c * 32 + j;       // global column

    __shared__ float sColD[Gg][Nn], sColH[Gg][Nn];
    __shared__ float sRowD[Gg][32], sRowH[Gg][32];

    // Load 8 owned cells; apply diagonal=0 and compute hops in registers
    float d[8], h[8];
    int base = b * Nn * Nn + r0 * Nn + jg;
    #pragma unroll
    for (int m = 0; m < 8; m++) {
        float dd = g_dist[base + m * Nn];
        if (r0 + m == jg) dd = 0.0f;
        d[m] = dd;
        h[m] = (r0 + m != jg && dd != CUDART_INF_F) ? 1.0f : 0.0f;
    }

    // Publish group 0 columns (owner CTA 0, local cols 0..7), initial state
    if (c == 0 && j < Gg) {
        __stcg(reinterpret_cast<float4*>(&g_stageD[0][b][j][r0]),
               make_float4(d[0], d[1], d[2], d[3]));
        __stcg(reinterpret_cast<float4*>(&g_stageD[0][b][j][r0 + 4]),
               make_float4(d[4], d[5], d[6], d[7]));
        __stcg(reinterpret_cast<float4*>(&g_stageH[0][b][j][r0]),
               make_float4(h[0], h[1], h[2], h[3]));
        __stcg(reinterpret_cast<float4*>(&g_stageH[0][b][j][r0 + 4]),
               make_float4(h[4], h[5], h[6], h[7]));
    }

    for (int q = 0; q < NGRP; q++) {
        int k0 = q * Gg;
        int slot = q & 1;
        CLUSTER_SYNC_();

        // Load column strips stage -> smem (512 float4 per array; 1024 thr)
        {
            int tt  = t & 511;
            int g   = tt >> 6;             // 64 float4 per column
            int i4  = (tt & 63) << 2;
            if (t < 512) {
                float4 v = __ldcg(reinterpret_cast<const float4*>(&g_stageD[slot][b][g][i4]));
                *reinterpret_cast<float4*>(&sColD[g][i4]) = v;
            } else {
                float4 v = __ldcg(reinterpret_cast<const float4*>(&g_stageH[slot][b][g][i4]));
                *reinterpret_cast<float4*>(&sColH[g][i4]) = v;
            }
        }
        // Row strips: rows k0..k0+7 live in one row-block's registers
        bool rowOwner = (rb == (k0 >> 3));
        if (rowOwner) {
            #pragma unroll
            for (int m = 0; m < 8; m++) { sRowD[m][j] = d[m]; sRowH[m][j] = h[m]; }
        }
        __syncthreads();

        #pragma unroll
        for (int g = 0; g < Gg; g++) {
            // main relax of 8 owned cells at global step k0+g
            float4 cd0 = *reinterpret_cast<const float4*>(&sColD[g][r0]);
            float4 cd1 = *reinterpret_cast<const float4*>(&sColD[g][r0 + 4]);
            float4 ch0 = *reinterpret_cast<const float4*>(&sColH[g][r0]);
            float4 ch1 = *reinterpret_cast<const float4*>(&sColH[g][r0 + 4]);
            float rd = sRowD[g][j];
            float rh = sRowH[g][j];
            float cd[8] = {cd0.x, cd0.y, cd0.z, cd0.w, cd1.x, cd1.y, cd1.z, cd1.w};
            float ch[8] = {ch0.x, ch0.y, ch0.z, ch0.w, ch1.x, ch1.y, ch1.z, ch1.w};
            #pragma unroll
            for (int m = 0; m < 8; m++) {
                float alt = __fadd_rn(cd[m], rd);
                if (alt < d[m]) {
                    float nh = __fadd_rn(ch[m], rh);
                    d[m] = alt;
                    h[m] = nh;
                    if (rowOwner && m > g) { sRowD[m][j] = alt; sRowH[m][j] = nh; }
                }
            }
            // column-strip completion for future steps (threads 0..255, i = t)
            if (t < Nn) {
                float cgd = sColD[g][t];
                float cgh = sColH[g][t];
                #pragma unroll
                for (int g2 = g + 1; g2 < Gg; g2++) {
                    float piv  = sColD[g2][k0 + g];   // d[k0+g][k0+g2] @ (k-1)-compl
                    float alt  = __fadd_rn(cgd, piv);
                    if (alt < sColD[g2][t]) {
                        sColD[g2][t] = alt;
                        sColH[g2][t] = __fadd_rn(cgh, sColH[g2][k0 + g]);
                    }
                }
            }
            __syncthreads();
        }

        // Publish next group's columns from owner's registers
        if (q < NGRP - 1) {
            int k0n = k0 + Gg;
            int s2  = slot ^ 1;
            if (c == (k0n >> 5)) {
                int jl0 = k0n & 31;
                if (j >= jl0 && j < jl0 + Gg) {
                    int g = j - jl0;
                    __stcg(reinterpret_cast<float4*>(&g_stageD[s2][b][g][r0]),
                           make_float4(d[0], d[1], d[2], d[3]));
                    __stcg(reinterpret_cast<float4*>(&g_stageD[s2][b][g][r0 + 4]),
                           make_float4(d[4], d[5], d[6], d[7]));
                    __stcg(reinterpret_cast<float4*>(&g_stageH[s2][b][g][r0]),
                           make_float4(h[0], h[1], h[2], h[3]));
                    __stcg(reinterpret_cast<float4*>(&g_stageH[s2][b][g][r0 + 4]),
                           make_float4(h[4], h[5], h[6], h[7]));
                }
            }
        }
    }

    // ---- fused epilogue: trip_times + reductions (double accumulation) ----
    double a_dt = 0, a_tr = 0, a_un = 0, a_td = 0, a_nd = 0;
    double a_b0 = 0, a_b1 = 0, a_b2 = 0, a_du = 0;

    #pragma unroll
    for (int m = 0; m < 8; m++) {
        int gi = base + m * Nn;
        float dd = d[m];
        float hh = h[m];
        float dem = demand[gi];
        bool np = (dd == CUDART_INF_F);
        float pl = np ? 0.0f : __fadd_rn(hh, 1.0f);
        float tr = (pl == 0.0f) ? 0.0f : __fsub_rn(pl, 2.0f);
        float tt = np ? 0.0f : __fadd_rn(dd, __fmul_rn(tr, 300.0f));
        out[OFF_TT + gi] = tt;
        double ddem = (double)dem;
        a_dt += ddem * (double)tt;
        a_tr += ddem * (double)tr;
        a_td += ddem;
        if (np) { a_un += ddem; if (dem > 0.0f) a_nd += 1.0; }
        if (tr == 0.0f)      a_b0 += ddem;
        else if (tr == 1.0f) a_b1 += ddem;
        else if (tr == 2.0f) a_b2 += ddem;
        else if (tr > 2.0f)  a_du += ddem;
    }

    a_dt = warp_sum_d(a_dt); a_tr = warp_sum_d(a_tr); a_un = warp_sum_d(a_un);
    a_td = warp_sum_d(a_td); a_nd = warp_sum_d(a_nd); a_b0 = warp_sum_d(a_b0);
    a_b1 = warp_sum_d(a_b1); a_b2 = warp_sum_d(a_b2); a_du = warp_sum_d(a_du);

    if (j == 0) {   // lane 0 of each warp
        atomicAdd(&g_acc[OFF_TDT + b], a_dt);
        atomicAdd(&g_acc[OFF_TTR + b], a_tr);
        atomicAdd(&g_acc[OFF_UNS + b], a_un);
        atomicAdd(&g_acc[OFF_TD  + b], a_td);
        atomicAdd(&g_acc[144 + b],     a_nd);
        atomicAdd(&g_acc[OFF_TAT + b * 4 + 0], a_b0);
        atomicAdd(&g_acc[OFF_TAT + b * 4 + 1], a_b1);
        atomicAdd(&g_acc[OFF_TAT + b * 4 + 2], a_b2);
        atomicAdd(&g_acc[OFF_TAT + b * 4 + 3], a_du + a_un);
    }
}

// ---------------------------------------------------------------------------
// Convert double accumulators to float outputs
// ---------------------------------------------------------------------------
__global__ void k_final(float* out) {
    int t = threadIdx.x;        // 160 threads
    if (t < 144)      out[t] = (float)g_acc[t];
    else if (t < 160) out[OFF_NDIS + (t - 144)] = (float)g_acc[t];
}

// ---------------------------------------------------------------------------
extern "C" void kernel_launch(void* const* d_in, const int* in_sizes, int n_in,
                              void* d_out, int out_size) {
    const float* dtm    = (const float*)d_in[0];
    const float* demand = (const float*)d_in[1];
    const int*   routes = (const int*)d_in[2];
    float* out = (float*)d_out;

    k_init<<<(Bn * Nn * Nn) / 256, 256>>>();
    k_edges<<<Bn * Rr, 32>>>(dtm, routes);
    fw_exact<<<Bn * CLU, THR>>>(demand, out);
    k_final<<<1, 160>>>(out);
}

// round 7
// speedup vs baseline: 1.9923x; 1.0774x over previous
#include <cuda_runtime.h>
#include <math_constants.h>

#define Bn 16
#define Nn 256
#define Rr 24
#define Ll 32
#define CLU 8            // CTAs per cluster (one cluster per batch)
#define THR 1024
#define Gg 8             // k-steps per cluster sync
#define NGRP (Nn / Gg)   // 32 groups

// Scratch (device globals; no allocation allowed)
__device__ float  g_dist[Bn * Nn * Nn];            // edge/dist matrix
__device__ float  g_stageD[2][Bn][Gg][Nn];         // column-strip broadcast, ping-pong
__device__ float  g_stageH[2][Bn][Gg][Nn];
__device__ double g_acc[160];                      // double accumulators

// Output layout (flattened tuple, float32):
#define OFF_TDT  0
#define OFF_TRT  16
#define OFF_TAT  32
#define OFF_TD   96
#define OFF_UNS  112
#define OFF_TTR  128
#define OFF_TT   144
#define OFF_NDIS (144 + Bn * Nn * Nn)
// g_acc layout: [0..143] same as out scalars, [144..159] n_disconnected

// ---------------------------------------------------------------------------
__global__ void k_init() {
    int idx = blockIdx.x * blockDim.x + threadIdx.x;   // exactly B*N*N threads
    g_dist[idx] = CUDART_INF_F;
    if (idx < 160) g_acc[idx] = 0.0;
}

// ---------------------------------------------------------------------------
// Edge build: one warp per (batch, route).
// Cumsum: XLA ReduceWindowRewriter blocked association, base_length = 16.
// ---------------------------------------------------------------------------
__global__ void k_edges(const float* __restrict__ dtm,
                        const int*   __restrict__ routes) {
    int br = blockIdx.x;
    int b = br / Rr;
    int lane = threadIdx.x;

    __shared__ int   ss[Ll];
    __shared__ float lf[Ll], lr[Ll];
    __shared__ float cf[Ll], cr[Ll];

    const int* rt = routes + br * Ll;
    int s = rt[lane];
    ss[lane] = s;
    __syncwarp();

    int snext = ss[(lane + 1 < Ll) ? lane + 1 : Ll - 1];
    float vf = 0.0f, vr = 0.0f;
    if (lane < Ll - 1) {
        vf = __fadd_rn(dtm[(b * Nn + s) * Nn + snext], 60.0f);
        vr = __fadd_rn(dtm[(b * Nn + snext) * Nn + s], 60.0f);
    }
    lf[lane] = vf;
    lr[lane] = vr;
    __syncwarp();

    if (lane == 0) {
        cf[0] = 0.0f; cr[0] = 0.0f;
        float a0f = 0.0f, a1f = 0.0f, Tf = 0.0f;
        float a0r = 0.0f, a1r = 0.0f, Tr = 0.0f;
        double srt = 0.0;
        #pragma unroll
        for (int m = 0; m < Ll - 1; m++) {
            if (m < 16) {
                a0f = __fadd_rn(a0f, lf[m]);
                a0r = __fadd_rn(a0r, lr[m]);
                cf[m + 1] = a0f;
                cr[m + 1] = a0r;
                if (m == 15) { Tf = a0f; Tr = a0r; }
            } else {
                a1f = __fadd_rn(a1f, lf[m]);
                a1r = __fadd_rn(a1r, lr[m]);
                cf[m + 1] = __fadd_rn(Tf, a1f);
                cr[m + 1] = __fadd_rn(Tr, a1r);
            }
            srt += (double)lf[m] + (double)lr[m];
        }
        atomicAdd(&g_acc[OFF_TRT + b], srt);       // total route time (double)
    }
    __syncwarp();

    unsigned int* eU = reinterpret_cast<unsigned int*>(g_dist);
    for (int p = lane; p < Ll * Ll; p += 32) {
        int i = p >> 5, j = p & 31;
        if (i < j) {
            int si = ss[i], sj = ss[j];
            float tf = __fsub_rn(cf[j], cf[i]);
            atomicMin(&eU[(b * Nn + si) * Nn + sj], __float_as_uint(tf));
            float tr = __fsub_rn(cr[j], cr[i]);
            atomicMin(&eU[(b * Nn + sj) * Nn + si], __float_as_uint(tr));
        }
    }
}

// ---------------------------------------------------------------------------
__device__ __forceinline__ double warp_sum_d(double v) {
    #pragma unroll
    for (int o = 16; o; o >>= 1) v += __shfl_down_sync(0xffffffffu, v, o);
    return v;
}

#define CLUSTER_SYNC_() do { \
    asm volatile("barrier.cluster.arrive.aligned;" ::: "memory"); \
    asm volatile("barrier.cluster.wait.aligned;" ::: "memory"); \
} while (0)

__global__ void __cluster_dims__(CLU, 1, 1) __launch_bounds__(THR, 1)
fw_exact(const float* __restrict__ demand, float* __restrict__ out) {
    int b = blockIdx.x / CLU;
    int c = blockIdx.x % CLU;
    int t = threadIdx.x;
    int j = t & 31;            // local column 0..31
    int rb = t >> 5;           // row block 0..31
    int r0 = rb << 3;          // first of 8 owned rows
    int jg = c * 32 + j;       // global column

    __shared__ float sColD[Gg][Nn], sColH[Gg][Nn];
    __shared__ float sRowD[Gg][32], sRowH[Gg][32];
    __shared__ float sMD[Gg * Gg], sMH[Gg * Gg];
    __shared__ float sProwD[Gg][Gg], sProwH[Gg][Gg];   // row g of P at round g
    __shared__ float sPcolD[Gg][Gg], sPcolH[Gg][Gg];   // col g of P at round g

    // Load 8 owned cells; diagonal=0; hops in registers
    float d[8], h[8];
    int base = b * Nn * Nn + r0 * Nn + jg;
    #pragma unroll
    for (int m = 0; m < 8; m++) {
        float dd = g_dist[base + m * Nn];
        if (r0 + m == jg) dd = 0.0f;
        d[m] = dd;
        h[m] = (r0 + m != jg && dd != CUDART_INF_F) ? 1.0f : 0.0f;
    }

    // Publish group 0 columns (owner CTA 0, local cols 0..7), initial state
    if (c == 0 && j < Gg) {
        __stcg(reinterpret_cast<float4*>(&g_stageD[0][b][j][r0]),
               make_float4(d[0], d[1], d[2], d[3]));
        __stcg(reinterpret_cast<float4*>(&g_stageD[0][b][j][r0 + 4]),
               make_float4(d[4], d[5], d[6], d[7]));
        __stcg(reinterpret_cast<float4*>(&g_stageH[0][b][j][r0]),
               make_float4(h[0], h[1], h[2], h[3]));
        __stcg(reinterpret_cast<float4*>(&g_stageH[0][b][j][r0 + 4]),
               make_float4(h[4], h[5], h[6], h[7]));
    }

    for (int q = 0; q < NGRP; q++) {
        int k0 = q * Gg;
        int slot = q & 1;
        CLUSTER_SYNC_();

        // ---- Phase A: load strips stage -> smem; warp 0 computes pivot block
        {
            int tt  = t & 511;
            int g   = tt >> 6;             // 64 float4 per column
            int i4  = (tt & 63) << 2;
            if (t < 512) {
                float4 v = __ldcg(reinterpret_cast<const float4*>(&g_stageD[slot][b][g][i4]));
                *reinterpret_cast<float4*>(&sColD[g][i4]) = v;
            } else {
                float4 v = __ldcg(reinterpret_cast<const float4*>(&g_stageH[slot][b][g][i4]));
                *reinterpret_cast<float4*>(&sColH[g][i4]) = v;
            }
        }
        if (t < 32) {
            // load 8x8 pivot block M (2 cells per lane)
            #pragma unroll
            for (int e = t; e < 64; e += 32) {
                int i = e >> 3, j2 = e & 7;
                sMD[e] = __ldcg(&g_stageD[slot][b][j2][k0 + i]);
                sMH[e] = __ldcg(&g_stageH[slot][b][j2][k0 + i]);
            }
            __syncwarp();
            #pragma unroll
            for (int g = 0; g < Gg; g++) {
                // snapshot row g & col g at (k0+g-1)-completion
                if (t < 8) {
                    sProwD[g][t] = sMD[g * 8 + t];
                    sProwH[g][t] = sMH[g * 8 + t];
                } else if (t < 16) {
                    int i = t - 8;
                    sPcolD[g][i] = sMD[i * 8 + g];
                    sPcolH[g][i] = sMH[i * 8 + g];
                }
                __syncwarp();
                // in-place step g (row g / col g invariant: diag is exactly 0)
                #pragma unroll
                for (int e = t; e < 64; e += 32) {
                    int i = e >> 3, j2 = e & 7;
                    float alt = __fadd_rn(sMD[i * 8 + g], sMD[g * 8 + j2]);
                    if (alt < sMD[e]) {
                        sMD[e] = alt;
                        sMH[e] = __fadd_rn(sMH[i * 8 + g], sMH[g * 8 + j2]);
                    }
                }
                __syncwarp();
            }
        }
        __syncthreads();   // strips + pivot tables ready

        // ---- Phase B: column completion (t<256, registers) + row completion
        if (t < Nn) {
            float cD[8], cH[8];
            #pragma unroll
            for (int g = 0; g < Gg; g++) { cD[g] = sColD[g][t]; cH[g] = sColH[g][t]; }
            #pragma unroll
            for (int g = 0; g < Gg - 1; g++) {
                #pragma unroll
                for (int g2 = g + 1; g2 < Gg; g2++) {
                    float alt = __fadd_rn(cD[g], sProwD[g][g2]);
                    if (alt < cD[g2]) {
                        cD[g2] = alt;
                        cH[g2] = __fadd_rn(cH[g], sProwH[g][g2]);
                    }
                }
            }
            #pragma unroll
            for (int g = 0; g < Gg; g++) { sColD[g][t] = cD[g]; sColH[g][t] = cH[g]; }
        }
        if (rb == (k0 >> 3)) {
            // complete rows k0..k0+7 (this thread holds them at column jg)
            #pragma unroll
            for (int g = 0; g < Gg - 1; g++) {
                #pragma unroll
                for (int m = g + 1; m < Gg; m++) {
                    float alt = __fadd_rn(sPcolD[g][m], d[g]);
                    if (alt < d[m]) {
                        d[m] = alt;
                        h[m] = __fadd_rn(sPcolH[g][m], h[g]);
                    }
                }
            }
            #pragma unroll
            for (int m = 0; m < Gg; m++) { sRowD[m][j] = d[m]; sRowH[m][j] = h[m]; }
        }
        __syncthreads();   // completed strips ready

        // ---- Phase C: main relax, 8 steps, no barriers
        #pragma unroll
        for (int g = 0; g < Gg; g++) {
            float4 cd0 = *reinterpret_cast<const float4*>(&sColD[g][r0]);
            float4 cd1 = *reinterpret_cast<const float4*>(&sColD[g][r0 + 4]);
            float4 ch0 = *reinterpret_cast<const float4*>(&sColH[g][r0]);
            float4 ch1 = *reinterpret_cast<const float4*>(&sColH[g][r0 + 4]);
            float rd = sRowD[g][j];
            float rh = sRowH[g][j];
            float cd[8] = {cd0.x, cd0.y, cd0.z, cd0.w, cd1.x, cd1.y, cd1.z, cd1.w};
            float ch[8] = {ch0.x, ch0.y, ch0.z, ch0.w, ch1.x, ch1.y, ch1.z, ch1.w};
            #pragma unroll
            for (int m = 0; m < 8; m++) {
                float alt = __fadd_rn(cd[m], rd);
                if (alt < d[m]) {
                    d[m] = alt;
                    h[m] = __fadd_rn(ch[m], rh);
                }
            }
        }

        // ---- Phase D: publish next group's columns from owner's registers
        if (q < NGRP - 1) {
            int k0n = k0 + Gg;
            int s2  = slot ^ 1;
            if (c == (k0n >> 5)) {
                int jl0 = k0n & 31;
                if (j >= jl0 && j < jl0 + Gg) {
                    int g = j - jl0;
                    __stcg(reinterpret_cast<float4*>(&g_stageD[s2][b][g][r0]),
                           make_float4(d[0], d[1], d[2], d[3]));
                    __stcg(reinterpret_cast<float4*>(&g_stageD[s2][b][g][r0 + 4]),
                           make_float4(d[4], d[5], d[6], d[7]));
                    __stcg(reinterpret_cast<float4*>(&g_stageH[s2][b][g][r0]),
                           make_float4(h[0], h[1], h[2], h[3]));
                    __stcg(reinterpret_cast<float4*>(&g_stageH[s2][b][g][r0 + 4]),
                           make_float4(h[4], h[5], h[6], h[7]));
                }
            }
        }
    }

    // ---- fused epilogue: trip_times + reductions (double accumulation) ----
    double a_dt = 0, a_tr = 0, a_un = 0, a_td = 0, a_nd = 0;
    double a_b0 = 0, a_b1 = 0, a_b2 = 0, a_du = 0;

    #pragma unroll
    for (int m = 0; m < 8; m++) {
        int gi = base + m * Nn;
        float dd = d[m];
        float hh = h[m];
        float dem = demand[gi];
        bool np = (dd == CUDART_INF_F);
        float pl = np ? 0.0f : __fadd_rn(hh, 1.0f);
        float tr = (pl == 0.0f) ? 0.0f : __fsub_rn(pl, 2.0f);
        float tt = np ? 0.0f : __fadd_rn(dd, __fmul_rn(tr, 300.0f));
        out[OFF_TT + gi] = tt;
        double ddem = (double)dem;
        a_dt += ddem * (double)tt;
        a_tr += ddem * (double)tr;
        a_td += ddem;
        if (np) { a_un += ddem; if (dem > 0.0f) a_nd += 1.0; }
        if (tr == 0.0f)      a_b0 += ddem;
        else if (tr == 1.0f) a_b1 += ddem;
        else if (tr == 2.0f) a_b2 += ddem;
        else if (tr > 2.0f)  a_du += ddem;
    }

    a_dt = warp_sum_d(a_dt); a_tr = warp_sum_d(a_tr); a_un = warp_sum_d(a_un);
    a_td = warp_sum_d(a_td); a_nd = warp_sum_d(a_nd); a_b0 = warp_sum_d(a_b0);
    a_b1 = warp_sum_d(a_b1); a_b2 = warp_sum_d(a_b2); a_du = warp_sum_d(a_du);

    if (j == 0) {   // lane 0 of each warp
        atomicAdd(&g_acc[OFF_TDT + b], a_dt);
        atomicAdd(&g_acc[OFF_TTR + b], a_tr);
        atomicAdd(&g_acc[OFF_UNS + b], a_un);
        atomicAdd(&g_acc[OFF_TD  + b], a_td);
        atomicAdd(&g_acc[144 + b],     a_nd);
        atomicAdd(&g_acc[OFF_TAT + b * 4 + 0], a_b0);
        atomicAdd(&g_acc[OFF_TAT + b * 4 + 1], a_b1);
        atomicAdd(&g_acc[OFF_TAT + b * 4 + 2], a_b2);
        atomicAdd(&g_acc[OFF_TAT + b * 4 + 3], a_du + a_un);
    }
}

// ---------------------------------------------------------------------------
__global__ void k_final(float* out) {
    int t = threadIdx.x;        // 160 threads
    if (t < 144)      out[t] = (float)g_acc[t];
    else if (t < 160) out[OFF_NDIS + (t - 144)] = (float)g_acc[t];
}

// ---------------------------------------------------------------------------
extern "C" void kernel_launch(void* const* d_in, const int* in_sizes, int n_in,
                              void* d_out, int out_size) {
    const float* dtm    = (const float*)d_in[0];
    const float* demand = (const float*)d_in[1];
    const int*   routes = (const int*)d_in[2];
    float* out = (float*)d_out;

    k_init<<<(Bn * Nn * Nn) / 256, 256>>>();
    k_edges<<<Bn * Rr, 32>>>(dtm, routes);
    fw_exact<<<Bn * CLU, THR>>>(demand, out);
    k_final<<<1, 160>>>(out);
}

// round 8
// speedup vs baseline: 2.0604x; 1.0341x over previous
#include <cuda_runtime.h>
#include <math_constants.h>

#define Bn 16
#define Nn 256
#define Rr 24
#define Ll 32
#define CLU 8            // CTAs per cluster (one cluster per batch)
#define THR 1024
#define Gg 8             // k-steps per cluster sync
#define NGRP (Nn / Gg)   // 32 groups

// Scratch (device globals; no allocation allowed)
__device__ float g_dist[Bn * Nn * Nn];             // edge matrix
__device__ float g_stageD[2][Bn][Gg][Nn];          // completed column strips, ping-pong
__device__ float g_stageH[2][Bn][Gg][Nn];
__device__ float g_acc[160];                       // scalar accumulators

// Output layout (flattened tuple, float32):
#define OFF_TDT  0
#define OFF_TRT  16
#define OFF_TAT  32
#define OFF_TD   96
#define OFF_UNS  112
#define OFF_TTR  128
#define OFF_TT   144
#define OFF_NDIS (144 + Bn * Nn * Nn)
// g_acc: [0..143] = out scalars, [144..159] = n_disconnected

// ---------------------------------------------------------------------------
__global__ void k_init() {
    int idx = blockIdx.x * blockDim.x + threadIdx.x;   // exactly B*N*N threads
    g_dist[idx] = CUDART_INF_F;
    if (idx < 160) g_acc[idx] = 0.0f;
}

// Dummy so fw_exact lands at launch index 3 (ncu capture slot)
__global__ void k_dummy() {}

// ---------------------------------------------------------------------------
// Edge build: one warp per (batch, route).
// Cumsum: XLA ReduceWindowRewriter blocked association, base_length = 16.
// ---------------------------------------------------------------------------
__global__ void k_edges(const float* __restrict__ dtm,
                        const int*   __restrict__ routes) {
    int br = blockIdx.x;
    int b = br / Rr;
    int lane = threadIdx.x;

    __shared__ int   ss[Ll];
    __shared__ float lf[Ll], lr[Ll];
    __shared__ float cf[Ll], cr[Ll];

    const int* rt = routes + br * Ll;
    int s = rt[lane];
    ss[lane] = s;
    __syncwarp();

    int snext = ss[(lane + 1 < Ll) ? lane + 1 : Ll - 1];
    float vf = 0.0f, vr = 0.0f;
    if (lane < Ll - 1) {
        vf = __fadd_rn(dtm[(b * Nn + s) * Nn + snext], 60.0f);
        vr = __fadd_rn(dtm[(b * Nn + snext) * Nn + s], 60.0f);
    }
    lf[lane] = vf;
    lr[lane] = vr;
    __syncwarp();

    if (lane == 0) {
        cf[0] = 0.0f; cr[0] = 0.0f;
        float a0f = 0.0f, a1f = 0.0f, Tf = 0.0f;
        float a0r = 0.0f, a1r = 0.0f, Tr = 0.0f;
        float srt = 0.0f;
        #pragma unroll
        for (int m = 0; m < Ll - 1; m++) {
            if (m < 16) {
                a0f = __fadd_rn(a0f, lf[m]);
                a0r = __fadd_rn(a0r, lr[m]);
                cf[m + 1] = a0f;
                cr[m + 1] = a0r;
                if (m == 15) { Tf = a0f; Tr = a0r; }
            } else {
                a1f = __fadd_rn(a1f, lf[m]);
                a1r = __fadd_rn(a1r, lr[m]);
                cf[m + 1] = __fadd_rn(Tf, a1f);
                cr[m + 1] = __fadd_rn(Tr, a1r);
            }
            srt += lf[m] + lr[m];
        }
        atomicAdd(&g_acc[OFF_TRT + b], srt);       // total route time
    }
    __syncwarp();

    unsigned int* eU = reinterpret_cast<unsigned int*>(g_dist);
    for (int p = lane; p < Ll * Ll; p += 32) {
        int i = p >> 5, j = p & 31;
        if (i < j) {
            int si = ss[i], sj = ss[j];
            float tf = __fsub_rn(cf[j], cf[i]);
            atomicMin(&eU[(b * Nn + si) * Nn + sj], __float_as_uint(tf));
            float tr = __fsub_rn(cr[j], cr[i]);
            atomicMin(&eU[(b * Nn + sj) * Nn + si], __float_as_uint(tr));
        }
    }
}

// ---------------------------------------------------------------------------
__device__ __forceinline__ float warp_sum(float v) {
    #pragma unroll
    for (int o = 16; o; o >>= 1) v += __shfl_down_sync(0xffffffffu, v, o);
    return v;
}

__global__ void __cluster_dims__(CLU, 1, 1) __launch_bounds__(THR, 1)
fw_exact(const float* __restrict__ demand, float* __restrict__ out) {
    int b = blockIdx.x / CLU;
    int c = blockIdx.x % CLU;
    int t = threadIdx.x;
    int j = t & 31;            // local column 0..31
    int rb = t >> 5;           // row block 0..31
    int r0 = rb << 3;          // first of 8 owned rows
    int jg = c * 32 + j;       // global column

    __shared__ float sColD[Gg][Nn], sColH[Gg][Nn];   // completed strips (also publisher staging)
    __shared__ float sRowD[Gg][32], sRowH[Gg][32];
    __shared__ float sMD[Gg * Gg], sMH[Gg * Gg];     // pivot block scratch
    __shared__ float sPD[Gg][Gg], sPH[Gg][Gg];       // row-g snapshots

    // Load 8 owned cells; diagonal=0; hops in registers
    float d[8], h[8];
    int base = b * Nn * Nn + r0 * Nn + jg;
    #pragma unroll
    for (int m = 0; m < 8; m++) {
        float dd = g_dist[base + m * Nn];
        if (r0 + m == jg) dd = 0.0f;
        d[m] = dd;
        h[m] = (r0 + m != jg && dd != CUDART_INF_F) ? 1.0f : 0.0f;
    }

    // Publisher routine: owner CTA completes next-group strips from its
    // registers and publishes them (bitwise-identical to R7's consumer-side
    // completion; validated by R6==R7 results).
    auto publish = [&](int s2, int k0n) {
        if (c == (k0n >> 5)) {
            int jl0 = k0n & 31;
            // 1. stage next 8 columns from registers into sCol (reused)
            if (j >= jl0 && j < jl0 + Gg) {
                int g = j - jl0;
                #pragma unroll
                for (int m = 0; m < 8; m++) {
                    sColD[g][r0 + m] = d[m];
                    sColH[g][r0 + m] = h[m];
                }
            }
            __syncthreads();
            // 2. warp 0: evolve 8x8 pivot block, snapshot row g pre-round
            if (t < 32) {
                #pragma unroll
                for (int e = t; e < 64; e += 32) {
                    int i = e >> 3, j2 = e & 7;
                    sMD[e] = sColD[j2][k0n + i];
                    sMH[e] = sColH[j2][k0n + i];
                }
                __syncwarp();
                #pragma unroll
                for (int g = 0; g < Gg; g++) {
                    if (t < 8) { sPD[g][t] = sMD[g * 8 + t]; sPH[g][t] = sMH[g * 8 + t]; }
                    __syncwarp();
                    #pragma unroll
                    for (int e = t; e < 64; e += 32) {
                        int i = e >> 3, j2 = e & 7;
                        float alt = __fadd_rn(sMD[i * 8 + g], sMD[g * 8 + j2]);
                        if (alt < sMD[e]) {
                            sMD[e] = alt;
                            sMH[e] = __fadd_rn(sMH[i * 8 + g], sMH[g * 8 + j2]);
                        }
                    }
                    __syncwarp();
                }
            }
            __syncthreads();
            // 3. column completion in registers (t < 256, one row each)
            if (t < Nn) {
                float cD[8], cH[8];
                #pragma unroll
                for (int g = 0; g < Gg; g++) { cD[g] = sColD[g][t]; cH[g] = sColH[g][t]; }
                #pragma unroll
                for (int g = 0; g < Gg - 1; g++) {
                    #pragma unroll
                    for (int g2 = g + 1; g2 < Gg; g2++) {
                        float alt = __fadd_rn(cD[g], sPD[g][g2]);
                        if (alt < cD[g2]) {
                            cD[g2] = alt;
                            cH[g2] = __fadd_rn(cH[g], sPH[g][g2]);
                        }
                    }
                }
                #pragma unroll
                for (int g = 0; g < Gg; g++) { sColD[g][t] = cD[g]; sColH[g][t] = cH[g]; }
            }
            __syncthreads();
            // 4. publish: 1024 threads, one float4 each
            {
                int g  = (t >> 6) & 7;
                int i4 = (t & 63) << 2;
                if (t < 512)
                    __stcg(reinterpret_cast<float4*>(&g_stageD[s2][b][g][i4]),
                           *reinterpret_cast<const float4*>(&sColD[g][i4]));
                else
                    __stcg(reinterpret_cast<float4*>(&g_stageH[s2][b][g][i4]),
                           *reinterpret_cast<const float4*>(&sColH[g][i4]));
            }
        }
    };

    // Pre-loop: CTA 0 publishes group 0 (initial-state columns 0..7)
    publish(0, 0);
    asm volatile("barrier.cluster.arrive.aligned;" ::: "memory");

    for (int q = 0; q < NGRP; q++) {
        int k0 = q * Gg;
        int slot = q & 1;
        asm volatile("barrier.cluster.wait.aligned;" ::: "memory");

        // load completed strips (1024 threads, one float4 each)
        {
            int g  = (t >> 6) & 7;
            int i4 = (t & 63) << 2;
            if (t < 512) {
                float4 v = __ldcg(reinterpret_cast<const float4*>(&g_stageD[slot][b][g][i4]));
                *reinterpret_cast<float4*>(&sColD[g][i4]) = v;
            } else {
                float4 v = __ldcg(reinterpret_cast<const float4*>(&g_stageH[slot][b][g][i4]));
                *reinterpret_cast<float4*>(&sColH[g][i4]) = v;
            }
        }
        __syncthreads();

        // row completion (row-block owner; pivot cols read from strips)
        if (rb == (k0 >> 3)) {
            #pragma unroll
            for (int g = 0; g < Gg - 1; g++) {
                #pragma unroll
                for (int m = g + 1; m < Gg; m++) {
                    float alt = __fadd_rn(sColD[g][k0 + m], d[g]);
                    if (alt < d[m]) {
                        d[m] = alt;
                        h[m] = __fadd_rn(sColH[g][k0 + m], h[g]);
                    }
                }
            }
            #pragma unroll
            for (int m = 0; m < Gg; m++) { sRowD[m][j] = d[m]; sRowH[m][j] = h[m]; }
        }
        __syncthreads();

        // main relax: 8 steps, straight-line
        #pragma unroll
        for (int g = 0; g < Gg; g++) {
            float4 cd0 = *reinterpret_cast<const float4*>(&sColD[g][r0]);
            float4 cd1 = *reinterpret_cast<const float4*>(&sColD[g][r0 + 4]);
            float4 ch0 = *reinterpret_cast<const float4*>(&sColH[g][r0]);
            float4 ch1 = *reinterpret_cast<const float4*>(&sColH[g][r0 + 4]);
            float rd = sRowD[g][j];
            float rh = sRowH[g][j];
            float cd[8] = {cd0.x, cd0.y, cd0.z, cd0.w, cd1.x, cd1.y, cd1.z, cd1.w};
            float ch[8] = {ch0.x, ch0.y, ch0.z, ch0.w, ch1.x, ch1.y, ch1.z, ch1.w};
            #pragma unroll
            for (int m = 0; m < 8; m++) {
                float alt = __fadd_rn(cd[m], rd);
                if (alt < d[m]) {
                    d[m] = alt;
                    h[m] = __fadd_rn(ch[m], rh);
                }
            }
        }

        if (q < NGRP - 1) {
            publish((q + 1) & 1, k0 + Gg);
            asm volatile("barrier.cluster.arrive.aligned;" ::: "memory");
        }
    }

    // ---- fused epilogue: trip_times + reductions ----
    float a_dt = 0, a_tr = 0, a_un = 0, a_td = 0, a_nd = 0;
    float a_b0 = 0, a_b1 = 0, a_b2 = 0, a_du = 0;

    #pragma unroll
    for (int m = 0; m < 8; m++) {
        int gi = base + m * Nn;
        float dd = d[m];
        float hh = h[m];
        float dem = demand[gi];
        bool np = (dd == CUDART_INF_F);
        float pl = np ? 0.0f : __fadd_rn(hh, 1.0f);
        float tr = (pl == 0.0f) ? 0.0f : __fsub_rn(pl, 2.0f);
        float tt = np ? 0.0f : __fadd_rn(dd, __fmul_rn(tr, 300.0f));
        out[OFF_TT + gi] = tt;
        a_dt += dem * tt;
        a_tr += dem * tr;
        a_td += dem;
        if (np) { a_un += dem; if (dem > 0.0f) a_nd += 1.0f; }
        if (tr == 0.0f)      a_b0 += dem;
        else if (tr == 1.0f) a_b1 += dem;
        else if (tr == 2.0f) a_b2 += dem;
        else if (tr > 2.0f)  a_du += dem;
    }

    a_dt = warp_sum(a_dt); a_tr = warp_sum(a_tr); a_un = warp_sum(a_un);
    a_td = warp_sum(a_td); a_nd = warp_sum(a_nd); a_b0 = warp_sum(a_b0);
    a_b1 = warp_sum(a_b1); a_b2 = warp_sum(a_b2); a_du = warp_sum(a_du);

    if (j == 0) {   // lane 0 of each warp
        atomicAdd(&g_acc[OFF_TDT + b], a_dt);
        atomicAdd(&g_acc[OFF_TTR + b], a_tr);
        atomicAdd(&g_acc[OFF_UNS + b], a_un);
        atomicAdd(&g_acc[OFF_TD  + b], a_td);
        atomicAdd(&g_acc[144 + b],     a_nd);
        atomicAdd(&g_acc[OFF_TAT + b * 4 + 0], a_b0);
        atomicAdd(&g_acc[OFF_TAT + b * 4 + 1], a_b1);
        atomicAdd(&g_acc[OFF_TAT + b * 4 + 2], a_b2);
        atomicAdd(&g_acc[OFF_TAT + b * 4 + 3], a_du + a_un);
    }
}

// ---------------------------------------------------------------------------
__global__ void k_final(float* out) {
    int t = threadIdx.x;        // 160 threads
    if (t < 144)      out[t] = g_acc[t];
    else if (t < 160) out[OFF_NDIS + (t - 144)] = g_acc[t];
}

// ---------------------------------------------------------------------------
extern "C" void kernel_launch(void* const* d_in, const int* in_sizes, int n_in,
                              void* d_out, int out_size) {
    const float* dtm    = (const float*)d_in[0];
    const float* demand = (const float*)d_in[1];
    const int*   routes = (const int*)d_in[2];
    float* out = (float*)d_out;

    k_init<<<(Bn * Nn * Nn) / 256, 256>>>();        // launch 0
    k_edges<<<Bn * Rr, 32>>>(dtm, routes);          // launch 1
    k_dummy<<<1, 32>>>();                           // launch 2 (ncu slot filler)
    fw_exact<<<Bn * CLU, THR>>>(demand, out);       // launch 3 (ncu captures this)
    k_final<<<1, 160>>>(out);                       // launch 4
}